// round 1
// baseline (speedup 1.0000x reference)
#include <cuda_runtime.h>
#include <math.h>

#define N_SPK 1024
#define N_UTT 20
#define D_EMB 512
#define ROWS (N_SPK * N_UTT)   // 20480

// ---------------- device scratch (no allocations allowed) ----------------
__device__ float g_en[(size_t)ROWS * D_EMB];    // normalized embeddings [20480, 512]
__device__ float g_cn[(size_t)N_SPK * D_EMB];   // normalized full centroids [1024, 512]
__device__ float g_diag[ROWS];                  // leave-one-out cosine per (n,m)
__device__ float g_expsum[ROWS];                // sum_k exp(w*(cos+eps)+b)

// ---------------- K0: zero accumulators ----------------
__global__ void zero_kernel() {
    int i = blockIdx.x * blockDim.x + threadIdx.x;
    if (i < ROWS) g_expsum[i] = 0.f;
}

// ---------------- K1: per-speaker prep ----------------
// One block per speaker. Computes sums, normalized centroid, normalized
// embeddings, and the leave-one-out diagonal cosine.
__global__ __launch_bounds__(256) void prep_kernel(const float* __restrict__ emb) {
    __shared__ float se[N_UTT][D_EMB];   // 40 KB
    __shared__ float ss[D_EMB];          // 2 KB
    __shared__ float red[256];

    int n = blockIdx.x;
    int tid = threadIdx.x;
    const float* E = emb + (size_t)n * N_UTT * D_EMB;

    for (int i = tid; i < N_UTT * D_EMB; i += 256)
        ((float*)se)[i] = E[i];
    __syncthreads();

    // sums over utterances
    for (int d = tid; d < D_EMB; d += 256) {
        float s = 0.f;
#pragma unroll
        for (int m = 0; m < N_UTT; m++) s += se[m][d];
        ss[d] = s;
    }
    __syncthreads();

    // centroid norm: c_n = (sums/M) / max(||sums/M||, 1e-8) = sums / max(||sums||, M*1e-8)
    float p = 0.f;
    for (int d = tid; d < D_EMB; d += 256) p += ss[d] * ss[d];
    red[tid] = p;
    __syncthreads();
    for (int off = 128; off > 0; off >>= 1) {
        if (tid < off) red[tid] += red[tid + off];
        __syncthreads();
    }
    float snorm = sqrtf(red[0]);
    float cscale = 1.f / fmaxf(snorm, (float)N_UTT * 1e-8f);
    for (int d = tid; d < D_EMB; d += 256)
        g_cn[(size_t)n * D_EMB + d] = ss[d] * cscale;

    // per-utterance: norms + leave-one-out cosine + normalized embedding
    int wid = tid >> 5, lane = tid & 31;
    for (int m = wid; m < N_UTT; m += 8) {
        float ee = 0.f, cc = 0.f, ec = 0.f;
        for (int d = lane; d < D_EMB; d += 32) {
            float e = se[m][d];
            float c = ss[d] - e;   // (M-1) * cent_excl
            ee += e * e;
            cc += c * c;
            ec += e * c;
        }
#pragma unroll
        for (int o = 16; o > 0; o >>= 1) {
            ee += __shfl_down_sync(0xffffffffu, ee, o);
            cc += __shfl_down_sync(0xffffffffu, cc, o);
            ec += __shfl_down_sync(0xffffffffu, ec, o);
        }
        ee = __shfl_sync(0xffffffffu, ee, 0);
        cc = __shfl_sync(0xffffffffu, cc, 0);
        ec = __shfl_sync(0xffffffffu, ec, 0);

        float ne  = sqrtf(ee);
        float ncl = sqrtf(cc) * (1.f / (float)(N_UTT - 1));  // ||cent_excl||
        if (lane == 0) {
            float dg = (ec * (1.f / (float)(N_UTT - 1))) /
                       (fmaxf(ne, 1e-8f) * fmaxf(ncl, 1e-8f));
            g_diag[n * N_UTT + m] = dg;
        }
        float esc = 1.f / fmaxf(ne, 1e-8f);
        for (int d = lane; d < D_EMB; d += 32)
            g_en[(size_t)(n * N_UTT + m) * D_EMB + d] = se[m][d] * esc;
    }
}

// ---------------- K2: fused SGEMM (NT) + exp-sum epilogue ----------------
// C[row, col] = dot(g_en[row,:], g_cn[col,:]); substitute diag when col==row/20,
// then accumulate exp(w*(C+1e-6)+b) per row into g_expsum.
#define BM 128
#define BN 128
#define BK 8

__global__ __launch_bounds__(256) void gemm_expsum_kernel(const float* __restrict__ wp,
                                                          const float* __restrict__ bp) {
    __shared__ float As[BK][BM + 4];
    __shared__ float Bs[BK][BN + 4];
    __shared__ float rowsum[BM];

    int bx = blockIdx.x;            // 0..7   column tiles (1024/128)
    int by = blockIdx.y;            // 0..159 row tiles (20480/128)
    int tid = threadIdx.x;
    int tx = tid & 15, ty = tid >> 4;

    int rowBase = by * BM;
    int colBase = bx * BN;

    float acc[8][8];
#pragma unroll
    for (int i = 0; i < 8; i++)
#pragma unroll
        for (int j = 0; j < 8; j++) acc[i][j] = 0.f;

    int lRow = tid >> 1;            // 0..127
    int lK   = (tid & 1) * 4;       // 0 or 4
    const float* Ag = g_en + (size_t)(rowBase + lRow) * D_EMB + lK;
    const float* Bg = g_cn + (size_t)(colBase + lRow) * D_EMB + lK;

    // register prefetch of first slab
    float4 av = *(const float4*)(Ag);
    float4 bv = *(const float4*)(Bg);

    for (int kt = 0; kt < D_EMB; kt += BK) {
        As[lK + 0][lRow] = av.x; As[lK + 1][lRow] = av.y;
        As[lK + 2][lRow] = av.z; As[lK + 3][lRow] = av.w;
        Bs[lK + 0][lRow] = bv.x; Bs[lK + 1][lRow] = bv.y;
        Bs[lK + 2][lRow] = bv.z; Bs[lK + 3][lRow] = bv.w;
        __syncthreads();

        if (kt + BK < D_EMB) {      // prefetch next slab during compute
            av = *(const float4*)(Ag + kt + BK);
            bv = *(const float4*)(Bg + kt + BK);
        }

#pragma unroll
        for (int kk = 0; kk < BK; kk++) {
            float ra[8], rb[8];
            *(float4*)(ra)     = *(const float4*)(&As[kk][ty * 8]);
            *(float4*)(ra + 4) = *(const float4*)(&As[kk][ty * 8 + 4]);
            *(float4*)(rb)     = *(const float4*)(&Bs[kk][tx * 8]);
            *(float4*)(rb + 4) = *(const float4*)(&Bs[kk][tx * 8 + 4]);
#pragma unroll
            for (int i = 0; i < 8; i++)
#pragma unroll
                for (int j = 0; j < 8; j++)
                    acc[i][j] = fmaf(ra[i], rb[j], acc[i][j]);
        }
        __syncthreads();
    }

    // epilogue: exp accumulation per row
    if (tid < BM) rowsum[tid] = 0.f;
    __syncthreads();

    float w = *wp, b = *bp;
    float b2 = fmaf(w, 1e-6f, b);   // folds the +SIM_EPS on the cosine

#pragma unroll
    for (int i = 0; i < 8; i++) {
        int rl = ty * 8 + i;
        int grow = rowBase + rl;
        int spk = grow / N_UTT;
        float dg = g_diag[grow];
        float ps = 0.f;
#pragma unroll
        for (int j = 0; j < 8; j++) {
            int col = colBase + tx * 8 + j;
            float v = (col == spk) ? dg : acc[i][j];
            ps += __expf(fmaf(w, v, b2));
        }
        atomicAdd(&rowsum[rl], ps);
    }
    __syncthreads();
    if (tid < BM) atomicAdd(&g_expsum[rowBase + tid], rowsum[tid]);
}

// ---------------- K3: final loss reduction ----------------
__global__ __launch_bounds__(256) void finalize_kernel(const float* __restrict__ wp,
                                                       const float* __restrict__ bp,
                                                       float* __restrict__ out) {
    __shared__ float red[256];
    int tid = threadIdx.x;
    float w = *wp, b = *bp;
    float s = 0.f;
    for (int r = tid; r < ROWS; r += 256) {
        float lse = logf(g_expsum[r] + 1e-6f);
        float pos = fmaf(w, g_diag[r] + 1e-6f, b);
        s += lse - pos;
    }
    red[tid] = s;
    __syncthreads();
    for (int off = 128; off > 0; off >>= 1) {
        if (tid < off) red[tid] += red[tid + off];
        __syncthreads();
    }
    if (tid == 0) out[0] = red[0];
}

// ---------------- launch ----------------
extern "C" void kernel_launch(void* const* d_in, const int* in_sizes, int n_in,
                              void* d_out, int out_size) {
    const float* emb = (const float*)d_in[0];
    const float* w   = (const float*)d_in[1];
    const float* b   = (const float*)d_in[2];
    float* out = (float*)d_out;

    zero_kernel<<<(ROWS + 255) / 256, 256>>>();
    prep_kernel<<<N_SPK, 256>>>(emb);
    dim3 g2(N_SPK / BN, ROWS / BM);   // (8, 160)
    gemm_expsum_kernel<<<g2, 256>>>(w, b);
    finalize_kernel<<<1, 256>>>(w, b, out);
}

// round 4
// speedup vs baseline: 5.9148x; 5.9148x over previous
#include <cuda_runtime.h>
#include <cuda_bf16.h>
#include <math.h>
#include <stdint.h>

#define N_SPK 1024
#define N_UTT 20
#define D_EMB 512
#define ROWS (N_SPK * N_UTT)   // 20480

// ---------------- device scratch ----------------
__device__ __nv_bfloat16 g_en_bf[(size_t)ROWS * D_EMB];   // normalized embeddings (bf16)
__device__ __nv_bfloat16 g_cn_bf[(size_t)N_SPK * D_EMB];  // normalized centroids (bf16)
__device__ float g_diag[ROWS];
__device__ float g_expsum[ROWS];
__device__ float g_part[80];

// ---------------- helpers ----------------
__device__ __forceinline__ uint32_t smem_u32(const void* p) {
    uint32_t a;
    asm("{ .reg .u64 t; cvta.to.shared.u64 t, %1; cvt.u32.u64 %0, t; }" : "=r"(a) : "l"(p));
    return a;
}
#define SWZ128(b) ((b) ^ (((b) >> 3) & 0x70))

#define CP_ASYNC16(dst, src) \
    asm volatile("cp.async.cg.shared.global [%0], [%1], 16;" :: "r"(dst), "l"(src))
#define CP_COMMIT()  asm volatile("cp.async.commit_group;" ::: "memory")
#define CP_WAIT0()   asm volatile("cp.async.wait_group 0;" ::: "memory")
#define CP_WAIT1()   asm volatile("cp.async.wait_group 1;" ::: "memory")

#define LDSM_X4(r0, r1, r2, r3, addr) \
    asm volatile("ldmatrix.sync.aligned.m8n8.x4.shared.b16 {%0,%1,%2,%3}, [%4];" \
                 : "=r"(r0), "=r"(r1), "=r"(r2), "=r"(r3) : "r"(addr))
#define LDSM_X2(r0, r1, addr) \
    asm volatile("ldmatrix.sync.aligned.m8n8.x2.shared.b16 {%0,%1}, [%2];" \
                 : "=r"(r0), "=r"(r1) : "r"(addr))

#define MMA_BF16(d, a0, a1, a2, a3, b0, b1) \
    asm volatile("mma.sync.aligned.m16n8k16.row.col.f32.bf16.bf16.f32 " \
                 "{%0,%1,%2,%3}, {%4,%5,%6,%7}, {%8,%9}, {%0,%1,%2,%3};" \
                 : "+f"((d)[0]), "+f"((d)[1]), "+f"((d)[2]), "+f"((d)[3]) \
                 : "r"(a0), "r"(a1), "r"(a2), "r"(a3), "r"(b0), "r"(b1))

// ---------------- K0: zero accumulators ----------------
__global__ void zero_kernel() {
    int i = blockIdx.x * blockDim.x + threadIdx.x;
    if (i < ROWS) g_expsum[i] = 0.f;
}

// ---------------- K1: per-speaker prep ----------------
__global__ __launch_bounds__(256) void prep_kernel(const float* __restrict__ emb) {
    __shared__ float se[N_UTT][D_EMB];   // 40 KB
    __shared__ float ss[D_EMB];
    __shared__ float red[256];

    int n = blockIdx.x;
    int tid = threadIdx.x;
    const float* E = emb + (size_t)n * N_UTT * D_EMB;

    for (int i = tid; i < N_UTT * D_EMB; i += 256)
        ((float*)se)[i] = E[i];
    __syncthreads();

    for (int d = tid; d < D_EMB; d += 256) {
        float s = 0.f;
#pragma unroll
        for (int m = 0; m < N_UTT; m++) s += se[m][d];
        ss[d] = s;
    }
    __syncthreads();

    float p = 0.f;
    for (int d = tid; d < D_EMB; d += 256) p += ss[d] * ss[d];
    red[tid] = p;
    __syncthreads();
    for (int off = 128; off > 0; off >>= 1) {
        if (tid < off) red[tid] += red[tid + off];
        __syncthreads();
    }
    float snorm = sqrtf(red[0]);
    float cscale = 1.f / fmaxf(snorm, (float)N_UTT * 1e-8f);
    for (int d = tid; d < D_EMB; d += 256)
        g_cn_bf[(size_t)n * D_EMB + d] = __float2bfloat16(ss[d] * cscale);

    int wid = tid >> 5, lane = tid & 31;
    for (int m = wid; m < N_UTT; m += 8) {
        float ee = 0.f, cc = 0.f, ec = 0.f;
        for (int d = lane; d < D_EMB; d += 32) {
            float e = se[m][d];
            float c = ss[d] - e;
            ee += e * e;
            cc += c * c;
            ec += e * c;
        }
#pragma unroll
        for (int o = 16; o > 0; o >>= 1) {
            ee += __shfl_down_sync(0xffffffffu, ee, o);
            cc += __shfl_down_sync(0xffffffffu, cc, o);
            ec += __shfl_down_sync(0xffffffffu, ec, o);
        }
        ee = __shfl_sync(0xffffffffu, ee, 0);
        cc = __shfl_sync(0xffffffffu, cc, 0);
        ec = __shfl_sync(0xffffffffu, ec, 0);

        float ne  = sqrtf(ee);
        float ncl = sqrtf(cc) * (1.f / (float)(N_UTT - 1));
        if (lane == 0) {
            float dg = (ec * (1.f / (float)(N_UTT - 1))) /
                       (fmaxf(ne, 1e-8f) * fmaxf(ncl, 1e-8f));
            g_diag[n * N_UTT + m] = dg;
        }
        float esc = 1.f / fmaxf(ne, 1e-8f);
        for (int d = lane; d < D_EMB; d += 32)
            g_en_bf[(size_t)(n * N_UTT + m) * D_EMB + d] = __float2bfloat16(se[m][d] * esc);
    }
}

// ---------------- K2: mma.sync bf16 GEMM + fused exp-sum epilogue ----------------
// Block tile 128x128, K chunks of 64, double-buffered cp.async.
// 8 warps: 2 (rows) x 4 (cols); warp tile 64x32 -> 4 m-frags x 4 n-frags of m16n8k16.
#define TILE_BYTES 16384           // 128 rows x 64 bf16 = 128B/row
#define A_OFF(s) ((s) * TILE_BYTES)
#define B_OFF(s) (32768 + (s) * TILE_BYTES)
#define RS_OFF   65536
#define SM_TOTAL (65536 + 512)

__global__ __launch_bounds__(256)
void gemm_expsum_kernel(const float* __restrict__ wp, const float* __restrict__ bp) {
    extern __shared__ char smem[];
    uint32_t sbase = smem_u32(smem);
    float* rowsum = (float*)(smem + RS_OFF);

    int tid = threadIdx.x;
    int wid = tid >> 5, lane = tid & 31;
    int wr = wid >> 2, wc = wid & 3;       // warp row (0..1), warp col (0..3)

    int rowBase = blockIdx.y * 128;
    int colBase = blockIdx.x * 128;

    const __nv_bfloat16* Ag = g_en_bf + (size_t)rowBase * D_EMB;
    const __nv_bfloat16* Bg = g_cn_bf + (size_t)colBase * D_EMB;

    // per-thread gmem->smem mapping: 4 iters x 16B for each of A and B
    int ldRow[4], ldG[4];
    uint32_t ldSw[4];
#pragma unroll
    for (int it = 0; it < 4; it++) {
        int id = it * 256 + tid;           // 0..1023 16B-chunks
        ldRow[it] = id >> 3;               // 0..127
        ldG[it] = id & 7;                  // 16B group in row
        ldSw[it] = SWZ128((uint32_t)(ldRow[it] * 128 + ldG[it] * 16));
    }

    float acc[4][4][4];
#pragma unroll
    for (int mi = 0; mi < 4; mi++)
#pragma unroll
        for (int ni = 0; ni < 4; ni++)
#pragma unroll
            for (int e = 0; e < 4; e++) acc[mi][ni][e] = 0.f;

    if (tid < 128) rowsum[tid] = 0.f;

    // ldmatrix addresses (offsets within a stage's tile)
    // A: row = wr*64 + mi*16 + (lane&7) + 8*((lane>>3)&1), col = ks*16 + 8*(lane>>4)
    // B: row = wc*32 + ni*8 + (lane&7),                    col = ks*16 + 8*((lane>>3)&1)
    int aRow0 = wr * 64 + (lane & 7) + 8 * ((lane >> 3) & 1);
    int aColQ = 8 * (lane >> 4);
    int bRow0 = wc * 32 + (lane & 7);
    int bColQ = 8 * ((lane >> 3) & 1);

    // ---- prologue: load chunk 0 into stage 0 ----
#pragma unroll
    for (int it = 0; it < 4; it++) {
        CP_ASYNC16(sbase + A_OFF(0) + ldSw[it], Ag + (size_t)ldRow[it] * D_EMB + ldG[it] * 8);
        CP_ASYNC16(sbase + B_OFF(0) + ldSw[it], Bg + (size_t)ldRow[it] * D_EMB + ldG[it] * 8);
    }
    CP_COMMIT();

    for (int c = 0; c < 8; c++) {
        int st = c & 1;
        if (c < 7) {
            int nst = (c + 1) & 1;
            const __nv_bfloat16* An = Ag + (c + 1) * 64;
            const __nv_bfloat16* Bn = Bg + (c + 1) * 64;
#pragma unroll
            for (int it = 0; it < 4; it++) {
                CP_ASYNC16(sbase + A_OFF(nst) + ldSw[it], An + (size_t)ldRow[it] * D_EMB + ldG[it] * 8);
                CP_ASYNC16(sbase + B_OFF(nst) + ldSw[it], Bn + (size_t)ldRow[it] * D_EMB + ldG[it] * 8);
            }
            CP_COMMIT();
            CP_WAIT1();
        } else {
            CP_WAIT0();
        }
        __syncthreads();

        uint32_t aBase = sbase + A_OFF(st);
        uint32_t bBase = sbase + B_OFF(st);
#pragma unroll
        for (int ks = 0; ks < 4; ks++) {
            uint32_t bfr[4][2];
#pragma unroll
            for (int ni = 0; ni < 4; ni++) {
                uint32_t addr = bBase + SWZ128((uint32_t)((bRow0 + ni * 8) * 128 +
                                                          (ks * 16 + bColQ) * 2));
                LDSM_X2(bfr[ni][0], bfr[ni][1], addr);
            }
#pragma unroll
            for (int mi = 0; mi < 4; mi++) {
                uint32_t a0, a1, a2, a3;
                uint32_t addr = aBase + SWZ128((uint32_t)((aRow0 + mi * 16) * 128 +
                                                          (ks * 16 + aColQ) * 2));
                LDSM_X4(a0, a1, a2, a3, addr);
#pragma unroll
                for (int ni = 0; ni < 4; ni++)
                    MMA_BF16(acc[mi][ni], a0, a1, a2, a3, bfr[ni][0], bfr[ni][1]);
            }
        }
        __syncthreads();
    }

    // ---- fused epilogue ----
    float w = *wp, b = *bp;
    float b2 = fmaf(w, 1e-6f, b);

#pragma unroll
    for (int mi = 0; mi < 4; mi++) {
#pragma unroll
        for (int h = 0; h < 2; h++) {
            int rl = wr * 64 + mi * 16 + (lane >> 2) + 8 * h;
            int grow = rowBase + rl;
            int spk = grow / N_UTT;
            float dg = g_diag[grow];
            float s = 0.f;
#pragma unroll
            for (int ni = 0; ni < 4; ni++) {
#pragma unroll
                for (int e = 0; e < 2; e++) {
                    int col = colBase + wc * 32 + ni * 8 + (lane & 3) * 2 + e;
                    float v = acc[mi][ni][h * 2 + e];
                    v = (col == spk) ? dg : v;
                    s += __expf(fmaf(w, v, b2));
                }
            }
            atomicAdd(&rowsum[rl], s);
        }
    }
    __syncthreads();
    if (tid < 128) atomicAdd(&g_expsum[rowBase + tid], rowsum[tid]);
}

// ---------------- K3a: partial lse sums (80 blocks) ----------------
__global__ __launch_bounds__(256) void lse_partial_kernel(const float* __restrict__ wp,
                                                          const float* __restrict__ bp) {
    __shared__ float red[256];
    int tid = threadIdx.x;
    int r = blockIdx.x * 256 + tid;
    float w = *wp, b = *bp;
    float lse = logf(g_expsum[r] + 1e-6f);
    float pos = fmaf(w, g_diag[r] + 1e-6f, b);
    red[tid] = lse - pos;
    __syncthreads();
    for (int off = 128; off > 0; off >>= 1) {
        if (tid < off) red[tid] += red[tid + off];
        __syncthreads();
    }
    if (tid == 0) g_part[blockIdx.x] = red[0];
}

// ---------------- K3b: final combine ----------------
__global__ void final_kernel(float* __restrict__ out) {
    __shared__ float red[128];
    int tid = threadIdx.x;
    float s = (tid < 80) ? g_part[tid] : 0.f;
    red[tid] = s;
    __syncthreads();
    for (int off = 64; off > 0; off >>= 1) {
        if (tid < off) red[tid] += red[tid + off];
        __syncthreads();
    }
    if (tid == 0) out[0] = red[0];
}

// ---------------- launch ----------------
extern "C" void kernel_launch(void* const* d_in, const int* in_sizes, int n_in,
                              void* d_out, int out_size) {
    const float* emb = (const float*)d_in[0];
    const float* w   = (const float*)d_in[1];
    const float* b   = (const float*)d_in[2];
    float* out = (float*)d_out;

    cudaFuncSetAttribute(gemm_expsum_kernel,
                         cudaFuncAttributeMaxDynamicSharedMemorySize, SM_TOTAL);

    zero_kernel<<<(ROWS + 255) / 256, 256>>>();
    prep_kernel<<<N_SPK, 256>>>(emb);
    dim3 g2(N_SPK / 128, ROWS / 128);   // (8, 160)
    gemm_expsum_kernel<<<g2, 256, SM_TOTAL>>>(w, b);
    lse_partial_kernel<<<80, 256>>>(w, b);
    final_kernel<<<1, 128>>>(out);
}